// round 14
// baseline (speedup 1.0000x reference)
#include <cuda_runtime.h>

#define S 64
#define D 128
#define ALPHA 0.2f
#define NWARP 16
#define THREADS 512

__global__ void __launch_bounds__(THREADS, 3)
gat_kernel(const float* __restrict__ center,
           const float* __restrict__ nbr,
           const float* __restrict__ a,
           float* __restrict__ out,
           int ngroups)
{
    // Double-buffered per-warp partials: one barrier per group instead of two.
    __shared__ float s_m[2][NWARP];
    __shared__ float s_sum[2][NWARP];
    __shared__ float s_acc[2][NWARP][D];   // 16 KB

    const int tid  = threadIdx.x;
    const int warp = tid >> 5;
    const int lane = tid & 31;

    // a[0:128] pairs with center, a[128:256] with nbr (loop-invariant).
    const float4 a1 = reinterpret_cast<const float4*>(a)[lane];
    const float4 a2 = reinterpret_cast<const float4*>(a)[32 + lane];

    const int stride = gridDim.x;
    int p = 0;

    for (int g = blockIdx.x; g < ngroups; g += stride) {
        // Each warp owns 4 consecutive rows of the 64-row group.
        const float4* __restrict__ cvec =
            reinterpret_cast<const float4*>(center) + (size_t)g * (S * D / 4) + warp * 4 * 32;
        const float4* __restrict__ nvec =
            reinterpret_cast<const float4*>(nbr)    + (size_t)g * (S * D / 4) + warp * 4 * 32;

        // ---- Phase 1: burst-load 4 c rows + 4 v rows; partial dots per lane.
        float4 v[4];
        float  d[4];
        #pragma unroll
        for (int i = 0; i < 4; i++) {
            const float4 c = __ldcs(&cvec[i * 32 + lane]);
            v[i]           = __ldcs(&nvec[i * 32 + lane]);
            d[i] = c.x * a1.x + c.y * a1.y + c.z * a1.z + c.w * a1.w
                 + v[i].x * a2.x + v[i].y * a2.y + v[i].z * a2.z + v[i].w * a2.w;
        }

        // ---- Phase 2: butterfly-reduce the 4 dots (off the load path). ----
        #pragma unroll
        for (int i = 0; i < 4; i++) {
            #pragma unroll
            for (int off = 16; off; off >>= 1)
                d[i] += __shfl_xor_sync(0xffffffffu, d[i], off);
        }

        // ---- Phase 3: per-warp softmax over 4 logits + weighted accumulate.
        float m = -1e30f;
        #pragma unroll
        for (int i = 0; i < 4; i++) {
            d[i] = (d[i] > 0.f) ? d[i] : ALPHA * d[i];   // leaky relu
            m = fmaxf(m, d[i]);
        }
        float sm = 0.f;
        float4 acc = make_float4(0.f, 0.f, 0.f, 0.f);
        #pragma unroll
        for (int i = 0; i < 4; i++) {
            const float pw = __expf(d[i] - m);
            sm += pw;
            acc.x += pw * v[i].x;
            acc.y += pw * v[i].y;
            acc.z += pw * v[i].z;
            acc.w += pw * v[i].w;
        }

        // Write partials into buffer p. The previous iteration's epilogue read
        // buffer p^1; iteration i+2 reuses p only after the i+1 barrier, which
        // the epilogue warps can only pass after finishing their reads. Safe
        // with a single barrier per iteration.
        if (lane == 0) { s_m[p][warp] = m; s_sum[p][warp] = sm; }
        reinterpret_cast<float4*>(s_acc[p][warp])[lane] = acc;
        __syncthreads();

        // ---- Phase 4: cross-warp combine; 128 threads, one feature each. ----
        if (tid < D) {
            float M = s_m[p][0];
            #pragma unroll
            for (int w = 1; w < NWARP; w++) M = fmaxf(M, s_m[p][w]);

            float tot = 0.f, o = 0.f;
            #pragma unroll
            for (int w = 0; w < NWARP; w++) {
                const float f = __expf(s_m[p][w] - M);
                tot += s_sum[p][w] * f;
                o   += s_acc[p][w][tid] * f;
            }
            out[(size_t)g * D + tid] = o * __frcp_rn(tot);
        }

        p ^= 1;
    }
}

extern "C" void kernel_launch(void* const* d_in, const int* in_sizes, int n_in,
                              void* d_out, int out_size)
{
    const float* center = (const float*)d_in[0];
    const float* nbr    = (const float*)d_in[1];
    const float* a      = (const float*)d_in[2];
    float* out          = (float*)d_out;

    const int ngroups = in_sizes[0] / (S * D);   // 8192

    int dev = 0, sms = 148;
    cudaGetDevice(&dev);
    cudaDeviceGetAttribute(&sms, cudaDevAttrMultiProcessorCount, dev);

    gat_kernel<<<3 * sms, THREADS>>>(center, nbr, a, out, ngroups);
}

// round 16
// speedup vs baseline: 1.0174x; 1.0174x over previous
#include <cuda_runtime.h>

#define S 64
#define D 128
#define ALPHA 0.2f
#define NWARP 16
#define THREADS 512

__global__ void __launch_bounds__(THREADS, 3)
gat_kernel(const float* __restrict__ center,
           const float* __restrict__ nbr,
           const float* __restrict__ a,
           float* __restrict__ out,
           int ngroups)
{
    // Double-buffered per-warp partials: one barrier per group instead of two.
    __shared__ float s_m[2][NWARP];
    __shared__ float s_sum[2][NWARP];
    __shared__ float s_acc[2][NWARP][D];   // 16 KB

    const int tid  = threadIdx.x;
    const int warp = tid >> 5;
    const int lane = tid & 31;

    // a[0:128] pairs with center, a[128:256] with nbr (loop-invariant).
    const float4 a1 = reinterpret_cast<const float4*>(a)[lane];
    const float4 a2 = reinterpret_cast<const float4*>(a)[32 + lane];

    const int stride = gridDim.x;
    int p = 0;

    for (int g = blockIdx.x; g < ngroups; g += stride) {
        // Each warp owns 4 consecutive rows of the 64-row group.
        const float4* __restrict__ cvec =
            reinterpret_cast<const float4*>(center) + (size_t)g * (S * D / 4) + warp * 4 * 32;
        const float4* __restrict__ nvec =
            reinterpret_cast<const float4*>(nbr)    + (size_t)g * (S * D / 4) + warp * 4 * 32;

        // ---- Phase 1: burst-load 4 c rows + 4 v rows; partial dots per lane.
        float4 v[4];
        float  d[4];
        #pragma unroll
        for (int i = 0; i < 4; i++) {
            const float4 c = __ldcs(&cvec[i * 32 + lane]);
            v[i]           = __ldcs(&nvec[i * 32 + lane]);
            d[i] = c.x * a1.x + c.y * a1.y + c.z * a1.z + c.w * a1.w
                 + v[i].x * a2.x + v[i].y * a2.y + v[i].z * a2.z + v[i].w * a2.w;
        }

        // ---- Phase 2: butterfly-reduce the 4 dots (off the load path). ----
        #pragma unroll
        for (int i = 0; i < 4; i++) {
            #pragma unroll
            for (int off = 16; off; off >>= 1)
                d[i] += __shfl_xor_sync(0xffffffffu, d[i], off);
        }

        // ---- Phase 3: per-warp softmax over 4 logits + weighted accumulate.
        float m = -1e30f;
        #pragma unroll
        for (int i = 0; i < 4; i++) {
            d[i] = (d[i] > 0.f) ? d[i] : ALPHA * d[i];   // leaky relu
            m = fmaxf(m, d[i]);
        }
        float sm = 0.f;
        float4 acc = make_float4(0.f, 0.f, 0.f, 0.f);
        #pragma unroll
        for (int i = 0; i < 4; i++) {
            const float pw = __expf(d[i] - m);
            sm += pw;
            acc.x += pw * v[i].x;
            acc.y += pw * v[i].y;
            acc.z += pw * v[i].z;
            acc.w += pw * v[i].w;
        }

        // Write partials into buffer p. The previous iteration's epilogue read
        // buffer p^1; iteration i+2 reuses p only after the i+1 barrier, which
        // the epilogue warps can only pass after finishing their reads. Safe
        // with a single barrier per iteration.
        if (lane == 0) { s_m[p][warp] = m; s_sum[p][warp] = sm; }
        reinterpret_cast<float4*>(s_acc[p][warp])[lane] = acc;
        __syncthreads();

        // ---- Phase 4: cross-warp combine; 128 threads, one feature each. ----
        if (tid < D) {
            float M = s_m[p][0];
            #pragma unroll
            for (int w = 1; w < NWARP; w++) M = fmaxf(M, s_m[p][w]);

            float tot = 0.f, o = 0.f;
            #pragma unroll
            for (int w = 0; w < NWARP; w++) {
                const float f = __expf(s_m[p][w] - M);
                tot += s_sum[p][w] * f;
                o   += s_acc[p][w][tid] * f;
            }
            out[(size_t)g * D + tid] = o * __frcp_rn(tot);
        }

        p ^= 1;
    }
}

extern "C" void kernel_launch(void* const* d_in, const int* in_sizes, int n_in,
                              void* d_out, int out_size)
{
    const float* center = (const float*)d_in[0];
    const float* nbr    = (const float*)d_in[1];
    const float* a      = (const float*)d_in[2];
    float* out          = (float*)d_out;

    const int ngroups = in_sizes[0] / (S * D);   // 8192

    int dev = 0, sms = 148;
    cudaGetDevice(&dev);
    cudaDeviceGetAttribute(&sms, cudaDevAttrMultiProcessorCount, dev);

    gat_kernel<<<3 * sms, THREADS>>>(center, nbr, a, out, ngroups);
}